// round 1
// baseline (speedup 1.0000x reference)
#include <cuda_runtime.h>
#include <math.h>

#define NB 4
#define NL 4096
#define ND 256
#define BLROWS (NB*NL)            // 16384
#define BLD (NB*NL*ND)            // 4194304
#define SCALE 0.0625f             // 256^-0.5

// ---- scratch (static device globals; allocation is forbidden) ----
__device__ float g_qr[BLD], g_qi[BLD], g_kr[BLD], g_ki[BLD], g_vr[BLD], g_vi[BLD];
__device__ float g_s[(size_t)NB*NL*NL];   // 268 MB scores/probs
__device__ float g_or[BLD], g_oi[BLD];

// ============================================================
// Kernel 1: projections  Y = X @ W^T + b   (M=16384, N=K=256)
// blockIdx.z selects which of the 6 projections.
// ============================================================
__global__ __launch_bounds__(256) void proj_kernel(
    const float* __restrict__ q_real, const float* __restrict__ q_imag,
    const float* __restrict__ k_real, const float* __restrict__ k_imag,
    const float* __restrict__ v_real, const float* __restrict__ v_imag,
    const float* __restrict__ Wq, const float* __restrict__ bq,
    const float* __restrict__ Wk, const float* __restrict__ bk,
    const float* __restrict__ Wv, const float* __restrict__ bv)
{
    const float *X, *W, *bias; float* Y;
    switch (blockIdx.z) {
      case 0: X=q_real; W=Wq; bias=bq; Y=g_qr; break;
      case 1: X=q_imag; W=Wq; bias=bq; Y=g_qi; break;
      case 2: X=k_real; W=Wk; bias=bk; Y=g_kr; break;
      case 3: X=k_imag; W=Wk; bias=bk; Y=g_ki; break;
      case 4: X=v_real; W=Wv; bias=bv; Y=g_vr; break;
      default: X=v_imag; W=Wv; bias=bv; Y=g_vi; break;
    }
    __shared__ float As[16][128];
    __shared__ float Bs[16][64];
    const int tid = threadIdx.x;
    const int tx = tid & 15, ty = tid >> 4;
    const int m0 = blockIdx.y * 128, n0 = blockIdx.x * 64;
    const int aRow = tid >> 2, aK = (tid & 3) << 2;
    float c[8][4] = {};
    for (int k0 = 0; k0 < ND; k0 += 16) {
        float4 a0 = *(const float4*)&X[(size_t)(m0+aRow   )*ND + k0 + aK];
        float4 a1 = *(const float4*)&X[(size_t)(m0+aRow+64)*ND + k0 + aK];
        float4 b0 = *(const float4*)&W[(size_t)(n0+aRow   )*ND + k0 + aK];
        __syncthreads();
        As[aK+0][aRow]=a0.x; As[aK+1][aRow]=a0.y; As[aK+2][aRow]=a0.z; As[aK+3][aRow]=a0.w;
        As[aK+0][aRow+64]=a1.x; As[aK+1][aRow+64]=a1.y; As[aK+2][aRow+64]=a1.z; As[aK+3][aRow+64]=a1.w;
        Bs[aK+0][aRow]=b0.x; Bs[aK+1][aRow]=b0.y; Bs[aK+2][aRow]=b0.z; Bs[aK+3][aRow]=b0.w;
        __syncthreads();
        #pragma unroll
        for (int k = 0; k < 16; k++) {
            float4 aA = *(const float4*)&As[k][ty*8];
            float4 aB = *(const float4*)&As[k][ty*8+4];
            float4 bb = *(const float4*)&Bs[k][tx*4];
            float av[8] = {aA.x,aA.y,aA.z,aA.w,aB.x,aB.y,aB.z,aB.w};
            float bv2[4] = {bb.x,bb.y,bb.z,bb.w};
            #pragma unroll
            for (int i = 0; i < 8; i++)
                #pragma unroll
                for (int j = 0; j < 4; j++)
                    c[i][j] = fmaf(av[i], bv2[j], c[i][j]);
        }
    }
    float4 b4 = *(const float4*)&bias[n0 + tx*4];
    #pragma unroll
    for (int i = 0; i < 8; i++) {
        float4 o;
        o.x = c[i][0]+b4.x; o.y = c[i][1]+b4.y; o.z = c[i][2]+b4.z; o.w = c[i][3]+b4.w;
        *(float4*)&Y[(size_t)(m0+ty*8+i)*ND + n0 + tx*4] = o;
    }
}

// ============================================================
// Kernel 2: scores  S = scale*(Qr Kr^T + Qi Ki^T)   per batch
// M=N=4096, K=256 per stream (two sequential phases)
// ============================================================
__global__ __launch_bounds__(256) void scores_kernel()
{
    const int b = blockIdx.z;
    const float* qrp = g_qr + (size_t)b*NL*ND;
    const float* qip = g_qi + (size_t)b*NL*ND;
    const float* krp = g_kr + (size_t)b*NL*ND;
    const float* kip = g_ki + (size_t)b*NL*ND;
    float* S = g_s + (size_t)b*NL*NL;

    __shared__ float As[16][128];
    __shared__ float Bs[16][64];
    const int tid = threadIdx.x;
    const int tx = tid & 15, ty = tid >> 4;
    const int m0 = blockIdx.y * 128, n0 = blockIdx.x * 64;
    const int aRow = tid >> 2, aK = (tid & 3) << 2;
    float c[8][4] = {};
    #pragma unroll
    for (int phase = 0; phase < 2; phase++) {
        const float* A  = phase ? qip : qrp;
        const float* Bm = phase ? kip : krp;
        for (int k0 = 0; k0 < ND; k0 += 16) {
            float4 a0 = *(const float4*)&A [(size_t)(m0+aRow   )*ND + k0 + aK];
            float4 a1 = *(const float4*)&A [(size_t)(m0+aRow+64)*ND + k0 + aK];
            float4 b0 = *(const float4*)&Bm[(size_t)(n0+aRow   )*ND + k0 + aK];
            __syncthreads();
            As[aK+0][aRow]=a0.x; As[aK+1][aRow]=a0.y; As[aK+2][aRow]=a0.z; As[aK+3][aRow]=a0.w;
            As[aK+0][aRow+64]=a1.x; As[aK+1][aRow+64]=a1.y; As[aK+2][aRow+64]=a1.z; As[aK+3][aRow+64]=a1.w;
            Bs[aK+0][aRow]=b0.x; Bs[aK+1][aRow]=b0.y; Bs[aK+2][aRow]=b0.z; Bs[aK+3][aRow]=b0.w;
            __syncthreads();
            #pragma unroll
            for (int k = 0; k < 16; k++) {
                float4 aA = *(const float4*)&As[k][ty*8];
                float4 aB = *(const float4*)&As[k][ty*8+4];
                float4 bb = *(const float4*)&Bs[k][tx*4];
                float av[8] = {aA.x,aA.y,aA.z,aA.w,aB.x,aB.y,aB.z,aB.w};
                float bv2[4] = {bb.x,bb.y,bb.z,bb.w};
                #pragma unroll
                for (int i = 0; i < 8; i++)
                    #pragma unroll
                    for (int j = 0; j < 4; j++)
                        c[i][j] = fmaf(av[i], bv2[j], c[i][j]);
            }
        }
    }
    #pragma unroll
    for (int i = 0; i < 8; i++) {
        float4 o;
        o.x = c[i][0]*SCALE; o.y = c[i][1]*SCALE; o.z = c[i][2]*SCALE; o.w = c[i][3]*SCALE;
        *(float4*)&S[(size_t)(m0+ty*8+i)*NL + n0 + tx*4] = o;
    }
}

// ============================================================
// Kernel 3: row softmax with pad mask (in place on g_s)
// one block = one row of 4096; 256 threads x 16 elems (reg-resident)
// ============================================================
__global__ __launch_bounds__(256) void softmax_kernel(const unsigned char* __restrict__ mask)
{
    __shared__ float sh[8];
    const int row = blockIdx.x;           // 0..16383
    const int b = row >> 12;
    float* S = g_s + (size_t)row * NL;
    const unsigned char* m = mask + (size_t)b * NL;
    const int t = threadIdx.x;

    float v[16];
    #pragma unroll
    for (int j = 0; j < 4; j++) {
        int f4 = t + j*256;               // float4 index
        float4 x = *(const float4*)&S[f4*4];
        uchar4 mk = *(const uchar4*)&m[f4*4];
        v[j*4+0] = mk.x ? -INFINITY : x.x;
        v[j*4+1] = mk.y ? -INFINITY : x.y;
        v[j*4+2] = mk.z ? -INFINITY : x.z;
        v[j*4+3] = mk.w ? -INFINITY : x.w;
    }
    float mx = -INFINITY;
    #pragma unroll
    for (int i = 0; i < 16; i++) mx = fmaxf(mx, v[i]);
    #pragma unroll
    for (int o = 16; o > 0; o >>= 1) mx = fmaxf(mx, __shfl_xor_sync(0xffffffffu, mx, o));
    if ((t & 31) == 0) sh[t >> 5] = mx;
    __syncthreads();
    mx = sh[0];
    #pragma unroll
    for (int i = 1; i < 8; i++) mx = fmaxf(mx, sh[i]);
    __syncthreads();

    float sum = 0.f;
    #pragma unroll
    for (int i = 0; i < 16; i++) { v[i] = __expf(v[i] - mx); sum += v[i]; }
    #pragma unroll
    for (int o = 16; o > 0; o >>= 1) sum += __shfl_xor_sync(0xffffffffu, sum, o);
    if ((t & 31) == 0) sh[t >> 5] = sum;
    __syncthreads();
    sum = 0.f;
    #pragma unroll
    for (int i = 0; i < 8; i++) sum += sh[i];
    const float inv = 1.f / sum;

    #pragma unroll
    for (int j = 0; j < 4; j++) {
        int f4 = t + j*256;
        float4 o;
        o.x = v[j*4+0]*inv; o.y = v[j*4+1]*inv; o.z = v[j*4+2]*inv; o.w = v[j*4+3]*inv;
        *(float4*)&S[f4*4] = o;
    }
}

// ============================================================
// Kernel 4: O = P @ V  (dual streams vr/vi share the P tile)
// per batch: M=4096, N=256, K=4096
// ============================================================
__global__ __launch_bounds__(256) void pv_kernel()
{
    const int b = blockIdx.z;
    const float* P  = g_s  + (size_t)b*NL*NL;
    const float* Vr = g_vr + (size_t)b*NL*ND;
    const float* Vi = g_vi + (size_t)b*NL*ND;
    float* Or = g_or + (size_t)b*NL*ND;
    float* Oi = g_oi + (size_t)b*NL*ND;

    __shared__ float As[16][128];
    __shared__ float Br[16][64];
    __shared__ float Bi[16][64];
    const int tid = threadIdx.x;
    const int tx = tid & 15, ty = tid >> 4;
    const int m0 = blockIdx.y * 128, n0 = blockIdx.x * 64;
    const int aRow = tid >> 2, aK = (tid & 3) << 2;
    const int bK = tid >> 4, bN = (tid & 15) << 2;
    float cr[8][4] = {}, ci[8][4] = {};

    for (int k0 = 0; k0 < NL; k0 += 16) {
        float4 a0 = *(const float4*)&P [(size_t)(m0+aRow   )*NL + k0 + aK];
        float4 a1 = *(const float4*)&P [(size_t)(m0+aRow+64)*NL + k0 + aK];
        float4 r0 = *(const float4*)&Vr[(size_t)(k0+bK)*ND + n0 + bN];
        float4 i0 = *(const float4*)&Vi[(size_t)(k0+bK)*ND + n0 + bN];
        __syncthreads();
        As[aK+0][aRow]=a0.x; As[aK+1][aRow]=a0.y; As[aK+2][aRow]=a0.z; As[aK+3][aRow]=a0.w;
        As[aK+0][aRow+64]=a1.x; As[aK+1][aRow+64]=a1.y; As[aK+2][aRow+64]=a1.z; As[aK+3][aRow+64]=a1.w;
        *(float4*)&Br[bK][bN] = r0;
        *(float4*)&Bi[bK][bN] = i0;
        __syncthreads();
        #pragma unroll
        for (int k = 0; k < 16; k++) {
            float4 aA = *(const float4*)&As[k][ty*8];
            float4 aB = *(const float4*)&As[k][ty*8+4];
            float4 br = *(const float4*)&Br[k][tx*4];
            float4 bi = *(const float4*)&Bi[k][tx*4];
            float av[8]  = {aA.x,aA.y,aA.z,aA.w,aB.x,aB.y,aB.z,aB.w};
            float brv[4] = {br.x,br.y,br.z,br.w};
            float biv[4] = {bi.x,bi.y,bi.z,bi.w};
            #pragma unroll
            for (int i = 0; i < 8; i++) {
                #pragma unroll
                for (int j = 0; j < 4; j++) {
                    cr[i][j] = fmaf(av[i], brv[j], cr[i][j]);
                    ci[i][j] = fmaf(av[i], biv[j], ci[i][j]);
                }
            }
        }
    }
    #pragma unroll
    for (int i = 0; i < 8; i++) {
        float4 o;
        o.x=cr[i][0]; o.y=cr[i][1]; o.z=cr[i][2]; o.w=cr[i][3];
        *(float4*)&Or[(size_t)(m0+ty*8+i)*ND + n0 + tx*4] = o;
        o.x=ci[i][0]; o.y=ci[i][1]; o.z=ci[i][2]; o.w=ci[i][3];
        *(float4*)&Oi[(size_t)(m0+ty*8+i)*ND + n0 + tx*4] = o;
    }
}

// ============================================================
// Kernel 5: layernorm over D=256 + final write
// grid.y = 0 -> real half of d_out, 1 -> imag half
// ============================================================
__global__ __launch_bounds__(256) void ln_kernel(
    const float* __restrict__ gamma, const float* __restrict__ beta,
    float* __restrict__ out)
{
    __shared__ float shs[8], shq[8];
    const int row = blockIdx.x;
    const int z = blockIdx.y;
    const float* X = (z ? g_oi : g_or) + (size_t)row * ND;
    const int t = threadIdx.x;
    float v = X[t];
    float s = v, q = v * v;
    #pragma unroll
    for (int o = 16; o > 0; o >>= 1) {
        s += __shfl_xor_sync(0xffffffffu, s, o);
        q += __shfl_xor_sync(0xffffffffu, q, o);
    }
    if ((t & 31) == 0) { shs[t >> 5] = s; shq[t >> 5] = q; }
    __syncthreads();
    s = 0.f; q = 0.f;
    #pragma unroll
    for (int i = 0; i < 8; i++) { s += shs[i]; q += shq[i]; }
    const float mean = s * (1.f/ND);
    const float var  = q * (1.f/ND) - mean * mean;
    const float rstd = rsqrtf(var + 1e-5f);
    out[(size_t)z*BLD + (size_t)row*ND + t] = (v - mean) * rstd * gamma[t] + beta[t];
}

// ============================================================
extern "C" void kernel_launch(void* const* d_in, const int* in_sizes, int n_in,
                              void* d_out, int out_size)
{
    (void)in_sizes; (void)n_in; (void)out_size;
    const float* q_real = (const float*)d_in[0];
    const float* q_imag = (const float*)d_in[1];
    const float* k_real = (const float*)d_in[2];
    const float* k_imag = (const float*)d_in[3];
    const float* v_real = (const float*)d_in[4];
    const float* v_imag = (const float*)d_in[5];
    const unsigned char* pad_mask = (const unsigned char*)d_in[6];
    const float* Wq = (const float*)d_in[7];
    const float* bq = (const float*)d_in[8];
    const float* Wk = (const float*)d_in[9];
    const float* bk = (const float*)d_in[10];
    const float* Wv = (const float*)d_in[11];
    const float* bv = (const float*)d_in[12];
    const float* gamma = (const float*)d_in[13];
    const float* beta  = (const float*)d_in[14];
    float* out = (float*)d_out;

    proj_kernel<<<dim3(ND/64, BLROWS/128, 6), 256>>>(
        q_real, q_imag, k_real, k_imag, v_real, v_imag,
        Wq, bq, Wk, bk, Wv, bv);
    scores_kernel<<<dim3(NL/64, NL/128, NB), 256>>>();
    softmax_kernel<<<dim3(NB*NL), 256>>>(pad_mask);
    pv_kernel<<<dim3(ND/64, NL/128, NB), 256>>>();
    ln_kernel<<<dim3(NB*NL, 2), 256>>>(gamma, beta, out);
}